// round 1
// baseline (speedup 1.0000x reference)
#include <cuda_runtime.h>
#include <math.h>
#include <float.h>

#define N 8192
#define D 512
#define KNN 16
#define NPAIRS 120   // 16*15/2

// ---------------- scratch (device globals; no runtime allocation) ----------
__device__ float g_sq[N];
__device__ float g_dist[(size_t)N * N];     // 256 MB full symmetric distance matrix
__device__ int   g_knn_idx[N * KNN];
__device__ float g_knn_d[N * KNN];
__device__ float g_curv_err[N];
__device__ float g_knn_sum[N];

// ---------------- K1: row squared norms ------------------------------------
__global__ void row_norms_kernel(const float* __restrict__ A) {
    int row = blockIdx.x;
    int t = threadIdx.x;                         // 128 threads, D/4 = 128
    const float4* a4 = (const float4*)(A + (size_t)row * D);
    float4 v = a4[t];
    float s = v.x * v.x + v.y * v.y + v.z * v.z + v.w * v.w;
    #pragma unroll
    for (int o = 16; o > 0; o >>= 1) s += __shfl_down_sync(0xffffffffu, s, o);
    __shared__ float red[4];
    if ((t & 31) == 0) red[t >> 5] = s;
    __syncthreads();
    if (t == 0) g_sq[row] = red[0] + red[1] + red[2] + red[3];
}

// ---------------- K2: symmetric distance GEMM ------------------------------
// C = A*A^T on upper-triangular 128x128 block tiles; epilogue converts to
// safe_sqrt distance and writes both (i,j) and (j,i) with float4 stores.
#define BM 128
#define BN 128
#define BK 16
#define TM 8
#define TN 8

__global__ __launch_bounds__(256, 2)
void dist_gemm_kernel(const float* __restrict__ A) {
    const int bi = blockIdx.y;
    const int bj = blockIdx.x;
    if (bi > bj) return;                 // symmetry: only upper-triangular blocks

    __shared__ float As[BK][BM + 4];
    __shared__ float Bs[BK][BN + 4];

    const int t  = threadIdx.x;
    const int tx = t & 15;               // 0..15 -> column group
    const int ty = t >> 4;               // 0..15 -> row group
    const int rowA0 = bi * BM;
    const int rowB0 = bj * BN;

    float acc[TM][TN];
    #pragma unroll
    for (int i = 0; i < TM; i++)
        #pragma unroll
        for (int j = 0; j < TN; j++) acc[i][j] = 0.f;

    for (int kt = 0; kt < D; kt += BK) {
        #pragma unroll
        for (int l = 0; l < 2; l++) {
            int idx = t + l * 256;       // 0..511
            int r   = idx >> 2;          // 0..127
            int c4  = idx & 3;           // 0..3
            float4 av = *(const float4*)(A + (size_t)(rowA0 + r) * D + kt + c4 * 4);
            As[c4 * 4 + 0][r] = av.x; As[c4 * 4 + 1][r] = av.y;
            As[c4 * 4 + 2][r] = av.z; As[c4 * 4 + 3][r] = av.w;
            float4 bv = *(const float4*)(A + (size_t)(rowB0 + r) * D + kt + c4 * 4);
            Bs[c4 * 4 + 0][r] = bv.x; Bs[c4 * 4 + 1][r] = bv.y;
            Bs[c4 * 4 + 2][r] = bv.z; Bs[c4 * 4 + 3][r] = bv.w;
        }
        __syncthreads();

        #pragma unroll
        for (int k = 0; k < BK; k++) {
            float ar[TM], br[TN];
            float4 a0 = *(const float4*)&As[k][ty * TM];
            float4 a1 = *(const float4*)&As[k][ty * TM + 4];
            ar[0]=a0.x; ar[1]=a0.y; ar[2]=a0.z; ar[3]=a0.w;
            ar[4]=a1.x; ar[5]=a1.y; ar[6]=a1.z; ar[7]=a1.w;
            float4 b0 = *(const float4*)&Bs[k][tx * TN];
            float4 b1 = *(const float4*)&Bs[k][tx * TN + 4];
            br[0]=b0.x; br[1]=b0.y; br[2]=b0.z; br[3]=b0.w;
            br[4]=b1.x; br[5]=b1.y; br[6]=b1.z; br[7]=b1.w;
            #pragma unroll
            for (int i = 0; i < TM; i++)
                #pragma unroll
                for (int j = 0; j < TN; j++)
                    acc[i][j] += ar[i] * br[j];
        }
        __syncthreads();
    }

    // epilogue: convert to distances in-place
    float sqi[TM], sqj[TN];
    #pragma unroll
    for (int i = 0; i < TM; i++) sqi[i] = g_sq[rowA0 + ty * TM + i];
    #pragma unroll
    for (int j = 0; j < TN; j++) sqj[j] = g_sq[rowB0 + tx * TN + j];

    #pragma unroll
    for (int i = 0; i < TM; i++)
        #pragma unroll
        for (int j = 0; j < TN; j++) {
            float d2 = sqi[i] + sqj[j] - 2.f * acc[i][j];
            acc[i][j] = (d2 > 0.f) ? sqrtf(fmaxf(d2, 1e-12f)) : 0.f;
        }

    // direct writes: row gi, cols rowB0+tx*8 .. +7  (float4 x2)
    #pragma unroll
    for (int i = 0; i < TM; i++) {
        int gi = rowA0 + ty * TM + i;
        float4 p0 = make_float4(acc[i][0], acc[i][1], acc[i][2], acc[i][3]);
        float4 p1 = make_float4(acc[i][4], acc[i][5], acc[i][6], acc[i][7]);
        float* dst = g_dist + (size_t)gi * N + rowB0 + tx * TN;
        *(float4*)(dst)     = p0;
        *(float4*)(dst + 4) = p1;
    }
    // mirror writes: row gj, cols rowA0+ty*8 .. +7  (float4 x2)
    #pragma unroll
    for (int j = 0; j < TN; j++) {
        int gj = rowB0 + tx * TN + j;
        float4 q0 = make_float4(acc[0][j], acc[1][j], acc[2][j], acc[3][j]);
        float4 q1 = make_float4(acc[4][j], acc[5][j], acc[6][j], acc[7][j]);
        float* dst = g_dist + (size_t)gj * N + rowA0 + ty * TM;
        *(float4*)(dst)     = q0;
        *(float4*)(dst + 4) = q1;
    }
}

// ---------------- K3: top-16 smallest per row (self excluded) --------------
__global__ __launch_bounds__(256)
void topk_kernel() {
    const int i = blockIdx.x;
    const int t = threadIdx.x;
    const float* __restrict__ drow = g_dist + (size_t)i * N;

    // per-thread register-resident top-16 over 32 strided candidates
    float v[KNN]; int id[KNN];
    #pragma unroll
    for (int u = 0; u < KNN; u++) { v[u] = FLT_MAX; id[u] = -1; }
    float vmax = FLT_MAX; int pmax = 0;

    for (int j = t; j < N; j += 256) {
        float dv = (j == i) ? FLT_MAX : drow[j];
        if (dv < vmax) {
            #pragma unroll
            for (int u = 0; u < KNN; u++)
                if (u == pmax) { v[u] = dv; id[u] = j; }
            float m = -1.f; int p = 0;
            #pragma unroll
            for (int u = 0; u < KNN; u++)
                if (v[u] > m) { m = v[u]; p = u; }
            vmax = m; pmax = p;
        }
    }

    __shared__ float sv[256 * KNN];
    __shared__ int   si[256 * KNN];
    __shared__ float rv[256];
    __shared__ int   rs[256];
    #pragma unroll
    for (int u = 0; u < KNN; u++) { sv[t * KNN + u] = v[u]; si[t * KNN + u] = id[u]; }
    __syncthreads();

    for (int r = 0; r < KNN; r++) {
        float mv = FLT_MAX; int ms = t * KNN;
        #pragma unroll
        for (int u = 0; u < KNN; u++) {
            float x = sv[t * KNN + u];
            if (x < mv) { mv = x; ms = t * KNN + u; }
        }
        rv[t] = mv; rs[t] = ms;
        __syncthreads();
        for (int s = 128; s > 0; s >>= 1) {
            if (t < s && rv[t + s] < rv[t]) { rv[t] = rv[t + s]; rs[t] = rs[t + s]; }
            __syncthreads();
        }
        if (t == 0) {
            int slot = rs[0];
            g_knn_d[i * KNN + r]   = rv[0];
            g_knn_idx[i * KNN + r] = si[slot];
            sv[slot] = FLT_MAX;      // remove winner
        }
        __syncthreads();
    }
}

// ---------------- K4: curvature per point ----------------------------------
// inter[j][k] = dist(idx_j, idx_k): a gather from the distance matrix.
__global__ __launch_bounds__(256)
void curvature_kernel(const float* __restrict__ ref_curv) {
    const int i = blockIdx.x;
    const int t = threadIdx.x;
    __shared__ int   nidx[KNN];
    __shared__ float nd[KNN];
    if (t < KNN) { nidx[t] = g_knn_idx[i * KNN + t]; nd[t] = g_knn_d[i * KNN + t]; }
    __syncthreads();

    int j = t >> 4, k = t & 15;              // 16x16 pair grid
    float inter = 0.f;
    if (j < k) inter = g_dist[(size_t)nidx[j] * N + nidx[k]];
    float dsum = (t < KNN) ? nd[t] : 0.f;

    __shared__ float r1[256], r2[256];
    r1[t] = inter; r2[t] = dsum;
    __syncthreads();
    for (int s = 128; s > 0; s >>= 1) {
        if (t < s) { r1[t] += r1[t + s]; r2[t] += r2[t + s]; }
        __syncthreads();
    }
    if (t == 0) {
        float avg        = r2[0] / (float)KNN;
        float inter_mean = r1[0] / (float)NPAIRS;
        float curv       = inter_mean / (avg + 1e-8f);
        float diff       = curv - ref_curv[i];
        g_curv_err[i] = diff * diff;
        g_knn_sum[i]  = r2[0];
    }
}

// ---------------- K5: final scalar (fp64 accumulation, deterministic) ------
__global__ void final_kernel(const float* __restrict__ ref_dist, float* __restrict__ out) {
    const int t = threadIdx.x;               // 256 threads
    double s_err = 0.0, s_knn = 0.0, s_ref = 0.0;
    for (int i = t; i < N; i += 256) { s_err += (double)g_curv_err[i]; s_knn += (double)g_knn_sum[i]; }
    for (int i = t; i < N * KNN; i += 256) s_ref += (double)ref_dist[i];
    __shared__ double d1[256], d2[256], d3[256];
    d1[t] = s_err; d2[t] = s_knn; d3[t] = s_ref;
    __syncthreads();
    for (int s = 128; s > 0; s >>= 1) {
        if (t < s) { d1[t] += d1[t + s]; d2[t] += d2[t + s]; d3[t] += d3[t + s]; }
        __syncthreads();
    }
    if (t == 0) {
        double curv_loss = d1[0] / (double)N;
        double m_knn = d2[0] / (double)(N * KNN);
        double m_ref = d3[0] / (double)(N * KNN);
        double diff  = m_knn - m_ref;
        out[0] = (float)(curv_loss + 0.1 * diff * diff);
    }
}

// ---------------- launch ----------------------------------------------------
extern "C" void kernel_launch(void* const* d_in, const int* in_sizes, int n_in,
                              void* d_out, int out_size) {
    const float* emb      = (const float*)d_in[0];   // [N, D]
    const float* ref_curv = (const float*)d_in[1];   // [N]
    const float* ref_dist = (const float*)d_in[2];   // [N, K]
    float* out = (float*)d_out;

    row_norms_kernel<<<N, 128>>>(emb);
    dim3 grid(N / BN, N / BM);
    dist_gemm_kernel<<<grid, 256>>>(emb);
    topk_kernel<<<N, 256>>>();
    curvature_kernel<<<N, 256>>>(ref_curv);
    final_kernel<<<1, 256>>>(ref_dist, out);
}